// round 5
// baseline (speedup 1.0000x reference)
#include <cuda_runtime.h>
#include <cstdint>
#include <cstddef>

#define SQ 2048
#define HIDN 2048
#define NHEAD 16
#define NKVH 4
#define HDIM 128
#define QKV_N 3072
#define RECENT_W 204
#define HEAVY_K 204

// ---------------- scratch (device globals; no allocations allowed) ----------
__device__ float g_qkv[SQ * QKV_N];                 // raw qkv projections
__device__ float g_q[NHEAD * SQ * HDIM];            // rotated q, [h][s][d]
__device__ float g_k[NKVH * SQ * HDIM];             // rotated k, [h][s][d]
__device__ float g_v[NKVH * SQ * HDIM];             // v, [h][s][d]
__device__ float g_e[NHEAD * SQ * SQ];              // scores, then exp(s - rowmax)
__device__ float g_invrsum[NHEAD * SQ];             // 1 / full-causal row sum
__device__ float g_colsum[NHEAD * SQ];              // softmax column sums
__device__ float g_invrsum2[NHEAD * SQ];            // 1 / masked row sum
__device__ unsigned char g_heavy[NHEAD * SQ];       // heavy-hitter column flags
__device__ float g_attnout[SQ * HIDN];              // attention output, [s][h*128+d]

// ---------------- warp reductions ----------------
static __device__ __forceinline__ float warp_red_max(float v) {
#pragma unroll
    for (int o = 16; o > 0; o >>= 1) v = fmaxf(v, __shfl_xor_sync(0xffffffffu, v, o));
    return v;
}
static __device__ __forceinline__ float warp_red_sum(float v) {
#pragma unroll
    for (int o = 16; o > 0; o >>= 1) v += __shfl_xor_sync(0xffffffffu, v, o);
    return v;
}

// ---------------- generic fp32 GEMM: C[M,N] = A[M,K] @ B[K,N] (+bias) -------
// 128x128 block tile, 8-deep k slice, 256 threads, 8x8 per-thread micro tile.
// Grid: (N/128, M/128). M,N multiples of 128; K multiple of 8.
__global__ __launch_bounds__(256) void gemm_kernel(
    const float* __restrict__ A, int lda,
    const float* __restrict__ B, int ldb,
    const float* __restrict__ bias,
    float* __restrict__ C, int ldc, int K)
{
    __shared__ float As[8][128];
    __shared__ float Bs[8][128];
    int tid = threadIdx.x;
    int row0 = blockIdx.y * 128, col0 = blockIdx.x * 128;
    int tr = tid >> 4, tc = tid & 15;
    float acc[8][8];
#pragma unroll
    for (int y = 0; y < 8; y++)
#pragma unroll
        for (int x = 0; x < 8; x++) acc[y][x] = 0.f;

    int am = (tid * 4) >> 3, ak = (tid * 4) & 7;      // A: 128 rows x 8 k
    int bk = (tid * 4) >> 7, bn = (tid * 4) & 127;    // B: 8 k x 128 cols
    const float* Aptr = A + (size_t)(row0 + am) * lda + ak;
    const float* Bptr = B + (size_t)bk * ldb + col0 + bn;

    for (int k0 = 0; k0 < K; k0 += 8) {
        float4 a4 = *(const float4*)(Aptr + k0);
        float4 b4 = *(const float4*)(Bptr + (size_t)k0 * ldb);
        As[ak + 0][am] = a4.x; As[ak + 1][am] = a4.y;
        As[ak + 2][am] = a4.z; As[ak + 3][am] = a4.w;
        *(float4*)&Bs[bk][bn] = b4;
        __syncthreads();
#pragma unroll
        for (int kk = 0; kk < 8; kk++) {
            float a[8], b[8];
#pragma unroll
            for (int x = 0; x < 8; x++) { a[x] = As[kk][tr * 8 + x]; b[x] = Bs[kk][tc * 8 + x]; }
#pragma unroll
            for (int y = 0; y < 8; y++)
#pragma unroll
                for (int x = 0; x < 8; x++) acc[y][x] = fmaf(a[y], b[x], acc[y][x]);
        }
        __syncthreads();
    }
#pragma unroll
    for (int y = 0; y < 8; y++) {
        int m = row0 + tr * 8 + y;
#pragma unroll
        for (int x = 0; x < 8; x++) {
            int n = col0 + tc * 8 + x;
            float val = acc[y][x];
            if (bias) val += bias[n];
            C[(size_t)m * ldc + n] = val;
        }
    }
}

// ---------------- RoPE + layout split -----------------
__global__ void rope_kernel(const float* __restrict__ cosp, const float* __restrict__ sinp) {
    int idx = blockIdx.x * blockDim.x + threadIdx.x;
    if (idx >= SQ * QKV_N) return;
    int s = idx / QKV_N, c = idx - s * QKV_N;
    float val = g_qkv[idx];
    if (c < 2048) {                       // q
        int h = c >> 7, d = c & 127;
        float cs = cosp[s * HDIM + d], sn = sinp[s * HDIM + d];
        float other = (d < 64) ? -g_qkv[idx + 64] : g_qkv[idx - 64];
        g_q[((size_t)h * SQ + s) * HDIM + d] = val * cs + other * sn;
    } else if (c < 2560) {                // k
        int cc = c - 2048, h = cc >> 7, d = cc & 127;
        float cs = cosp[s * HDIM + d], sn = sinp[s * HDIM + d];
        float other = (d < 64) ? -g_qkv[idx + 64] : g_qkv[idx - 64];
        g_k[((size_t)h * SQ + s) * HDIM + d] = val * cs + other * sn;
    } else {                              // v
        int cc = c - 2560, h = cc >> 7, d = cc & 127;
        g_v[((size_t)h * SQ + s) * HDIM + d] = val;
    }
}

// ---------------- scores = scale * q @ k^T, causal (only j<=i written) ------
__global__ __launch_bounds__(256) void qk_kernel() {
    if (blockIdx.x > blockIdx.y) return;   // fully above diagonal
    int h = blockIdx.z;
    int i0 = blockIdx.y * 128, j0 = blockIdx.x * 128;
    const float* Q  = g_q + (size_t)h * SQ * HDIM;
    const float* Kp = g_k + (size_t)(h >> 2) * SQ * HDIM;
    __shared__ float Qs[8][128];
    __shared__ float Ks[8][128];
    int tid = threadIdx.x;
    int tr = tid >> 4, tc = tid & 15;
    float acc[8][8];
#pragma unroll
    for (int y = 0; y < 8; y++)
#pragma unroll
        for (int x = 0; x < 8; x++) acc[y][x] = 0.f;

    int am = (tid * 4) >> 3, ak = (tid * 4) & 7;
    for (int d0 = 0; d0 < HDIM; d0 += 8) {
        float4 qa = *(const float4*)&Q[(size_t)(i0 + am) * HDIM + d0 + ak];
        float4 ka = *(const float4*)&Kp[(size_t)(j0 + am) * HDIM + d0 + ak];
        Qs[ak + 0][am] = qa.x; Qs[ak + 1][am] = qa.y; Qs[ak + 2][am] = qa.z; Qs[ak + 3][am] = qa.w;
        Ks[ak + 0][am] = ka.x; Ks[ak + 1][am] = ka.y; Ks[ak + 2][am] = ka.z; Ks[ak + 3][am] = ka.w;
        __syncthreads();
#pragma unroll
        for (int kk = 0; kk < 8; kk++) {
            float a[8], b[8];
#pragma unroll
            for (int x = 0; x < 8; x++) { a[x] = Qs[kk][tr * 8 + x]; b[x] = Ks[kk][tc * 8 + x]; }
#pragma unroll
            for (int y = 0; y < 8; y++)
#pragma unroll
                for (int x = 0; x < 8; x++) acc[y][x] = fmaf(a[y], b[x], acc[y][x]);
        }
        __syncthreads();
    }
    const float scale = 0.08838834764831845f;  // 1/sqrt(128)
    float* E = g_e + (size_t)h * SQ * SQ;
#pragma unroll
    for (int y = 0; y < 8; y++) {
        int i = i0 + tr * 8 + y;
#pragma unroll
        for (int x = 0; x < 8; x++) {
            int j = j0 + tc * 8 + x;
            if (j <= i) E[(size_t)i * SQ + j] = acc[y][x] * scale;
        }
    }
}

// ---------------- per-row: max, e = exp(s-m) in place, 1/sum ----------------
__global__ void rowexp_kernel() {
    int i = blockIdx.x, h = blockIdx.y, tid = threadIdx.x;   // 128 threads
    float* row = g_e + ((size_t)h * SQ + i) * SQ;
    int n = i + 1;
    float m = -1e30f;
    for (int j = tid; j < n; j += 128) m = fmaxf(m, row[j]);
    __shared__ float red[4];
    m = warp_red_max(m);
    if ((tid & 31) == 0) red[tid >> 5] = m;
    __syncthreads();
    m = fmaxf(fmaxf(red[0], red[1]), fmaxf(red[2], red[3]));
    float ssum = 0.f;
    for (int j = tid; j < n; j += 128) { float e = __expf(row[j] - m); row[j] = e; ssum += e; }
    __syncthreads();
    ssum = warp_red_sum(ssum);
    if ((tid & 31) == 0) red[tid >> 5] = ssum;
    __syncthreads();
    if (tid == 0) g_invrsum[h * SQ + i] = 1.0f / (red[0] + red[1] + red[2] + red[3]);
}

// ---------------- column sums of the full-causal softmax --------------------
__global__ void colsum_kernel() {
    int h = blockIdx.y;
    int j = blockIdx.x * 256 + threadIdx.x;
    int istart = blockIdx.x * 256;               // min j in block
    const float* E = g_e + (size_t)h * SQ * SQ;
    float acc = 0.f;
    for (int i = istart; i < SQ; i++) {
        if (i >= j) acc += E[(size_t)i * SQ + j] * g_invrsum[h * SQ + i];
    }
    g_colsum[h * SQ + j] = acc;
}

// ---------------- per-head top-204 threshold via bitonic sort ---------------
__global__ __launch_bounds__(1024) void topk_kernel() {
    __shared__ float sv[2048];
    int h = blockIdx.x, tid = threadIdx.x;       // 1024 threads
    sv[tid] = g_colsum[h * SQ + tid];
    sv[tid + 1024] = g_colsum[h * SQ + tid + 1024];
    __syncthreads();
    for (int k = 2; k <= 2048; k <<= 1) {
        for (int j = k >> 1; j > 0; j >>= 1) {
#pragma unroll 2
            for (int base = 0; base < 2048; base += 1024) {
                int i = base + tid;
                int l = i ^ j;
                if (l > i) {
                    float a = sv[i], b = sv[l];
                    bool up = ((i & k) == 0);
                    if ((a > b) == up) { sv[i] = b; sv[l] = a; }
                }
            }
            __syncthreads();
        }
    }
    float thr = sv[2048 - HEAVY_K];              // 204th largest
    g_heavy[h * SQ + tid]        = (g_colsum[h * SQ + tid]        >= thr) ? 1 : 0;
    g_heavy[h * SQ + tid + 1024] = (g_colsum[h * SQ + tid + 1024] >= thr) ? 1 : 0;
}

// ---------------- masked row sums (second softmax denominator) --------------
__global__ void rowsum2_kernel() {
    int i = blockIdx.x, h = blockIdx.y, tid = threadIdx.x;   // 128 threads
    const float* row = g_e + ((size_t)h * SQ + i) * SQ;
    const unsigned char* hv = g_heavy + h * SQ;
    float s = 0.f;
    for (int j = tid; j <= i; j += 128) {
        if (hv[j] || (i - j) <= RECENT_W) s += row[j];
    }
    __shared__ float red[4];
    s = warp_red_sum(s);
    if ((tid & 31) == 0) red[tid >> 5] = s;
    __syncthreads();
    if (tid == 0) g_invrsum2[h * SQ + i] = 1.0f / (red[0] + red[1] + red[2] + red[3]);
}

// ---------------- out = P_masked @ V  (P generated on the fly) --------------
__global__ __launch_bounds__(256) void av_kernel() {
    int h = blockIdx.y;
    int q0 = blockIdx.x * 128;
    const float* E = g_e + (size_t)h * SQ * SQ;
    const float* V = g_v + (size_t)(h >> 2) * SQ * HDIM;
    const unsigned char* hv = g_heavy + h * SQ;
    __shared__ float Ps[8][128];
    __shared__ float Vs[8][128];
    __shared__ float sinv[128];
    int tid = threadIdx.x;
    if (tid < 128) sinv[tid] = g_invrsum2[h * SQ + q0 + tid];
    __syncthreads();
    int tr = tid >> 4, tc = tid & 15;
    float acc[8][8];
#pragma unroll
    for (int y = 0; y < 8; y++)
#pragma unroll
        for (int x = 0; x < 8; x++) acc[y][x] = 0.f;

    int pq = (tid * 4) >> 3, pj = (tid * 4) & 7;
    int vk = (tid * 4) >> 7, vd = (tid * 4) & 127;
    int jend = q0 + 128;                   // causal: j <= q < q0+128
    for (int j0 = 0; j0 < jend; j0 += 8) {
        int qg = q0 + pq;
        float inv = sinv[pq];
#pragma unroll
        for (int t = 0; t < 4; t++) {
            int jg = j0 + pj + t;
            float p = 0.f;
            if (jg <= qg && (hv[jg] || (qg - jg) <= RECENT_W))
                p = E[(size_t)qg * SQ + jg] * inv;
            Ps[pj + t][pq] = p;
        }
        float4 v4 = *(const float4*)&V[(size_t)(j0 + vk) * HDIM + vd];
        *(float4*)&Vs[vk][vd] = v4;
        __syncthreads();
#pragma unroll
        for (int kk = 0; kk < 8; kk++) {
            float a[8], b[8];
#pragma unroll
            for (int x = 0; x < 8; x++) { a[x] = Ps[kk][tr * 8 + x]; b[x] = Vs[kk][tc * 8 + x]; }
#pragma unroll
            for (int y = 0; y < 8; y++)
#pragma unroll
                for (int x = 0; x < 8; x++) acc[y][x] = fmaf(a[y], b[x], acc[y][x]);
        }
        __syncthreads();
    }
#pragma unroll
    for (int y = 0; y < 8; y++) {
        int qg = q0 + tr * 8 + y;
#pragma unroll
        for (int x = 0; x < 8; x++) {
            int d = tc * 8 + x;
            g_attnout[(size_t)qg * HIDN + h * HDIM + d] = acc[y][x];
        }
    }
}

// ---------------- launch ----------------
extern "C" void kernel_launch(void* const* d_in, const int* in_sizes, int n_in,
                              void* d_out, int out_size) {
    (void)in_sizes; (void)n_in; (void)out_size;
    const float* hidden = (const float*)d_in[0];
    const float* cosp   = (const float*)d_in[1];
    const float* sinp   = (const float*)d_in[2];
    // d_in[3] attention_mask: causal, reproduced analytically
    const float* Wq = (const float*)d_in[4];
    const float* bq = (const float*)d_in[5];
    const float* Wk = (const float*)d_in[6];
    const float* bk = (const float*)d_in[7];
    const float* Wv = (const float*)d_in[8];
    const float* bv = (const float*)d_in[9];
    const float* Wo = (const float*)d_in[10];
    float* out = (float*)d_out;

    void* p;
    cudaGetSymbolAddress(&p, g_qkv);     float* qkv     = (float*)p;
    cudaGetSymbolAddress(&p, g_attnout); float* attnout = (float*)p;

    // QKV projections (+bias)
    gemm_kernel<<<dim3(16, 16), 256>>>(hidden, HIDN, Wq, 2048, bq, qkv,        QKV_N, HIDN);
    gemm_kernel<<<dim3(4, 16),  256>>>(hidden, HIDN, Wk,  512, bk, qkv + 2048, QKV_N, HIDN);
    gemm_kernel<<<dim3(4, 16),  256>>>(hidden, HIDN, Wv,  512, bv, qkv + 2560, QKV_N, HIDN);

    rope_kernel<<<(SQ * QKV_N + 255) / 256, 256>>>(cosp, sinp);

    qk_kernel<<<dim3(16, 16, NHEAD), 256>>>();
    rowexp_kernel<<<dim3(SQ, NHEAD), 128>>>();
    colsum_kernel<<<dim3(8, NHEAD), 256>>>();
    topk_kernel<<<NHEAD, 1024>>>();
    rowsum2_kernel<<<dim3(SQ, NHEAD), 128>>>();
    av_kernel<<<dim3(16, NHEAD), 256>>>();

    // output projection
    gemm_kernel<<<dim3(16, 16), 256>>>(attnout, HIDN, Wo, HIDN, (const float*)nullptr, out, HIDN, HIDN);
}